// round 12
// baseline (speedup 1.0000x reference)
#include <cuda_runtime.h>

#define NRK 4
#define DW  64
#define KD  256            // NR*D plane stride
#define THREADS 256
#define NB  512            // value buckets (width 1/64 over [-4,4])
#define ES  8              // elements per thread (contiguous chunk), Nt,Ns <= 2048
#define PAD 2048
#define ALM_BLOCKS 8
#define NMAX 2048          // padded column stride
#define TOTAL_BLOCKS (KD + ALM_BLOCKS)

// Static scratch (no allocation). Zero-init at load; pads never written -> 0.
__device__ float  g_sT[KD * NMAX];           // s transposed+padded: [KD][NMAX]
__device__ float  g_tT[KD * NMAX];           // t transposed+padded: [KD][NMAX]
__device__ double g_colp[KD];                // per-column partials
__device__ double g_almp[ALM_BLOCKS * NRK];  // per-block per-k anchor partials
__device__ int    g_count = 0;               // completion ticket (self-reset)

// ---------------- tiled transpose: [N][256] -> [256][NMAX] ----------------
__global__ void transpose_kernel(const float* __restrict__ s,
                                 const float* __restrict__ t,
                                 int Ns, int Nt) {
    __shared__ float tile[32][33];
    const float* src; float* dst; int N;
    if (blockIdx.z == 0) { src = s; dst = g_sT; N = Ns; }
    else                 { src = t; dst = g_tT; N = Nt; }
    const int tx = threadIdx.x, ty = threadIdx.y;  // 32 x 8
    const int r0 = blockIdx.x * 32, c0 = blockIdx.y * 32;
    #pragma unroll
    for (int i = 0; i < 4; i++) {
        int r = r0 + ty + i * 8;
        if (r < N) tile[ty + i * 8][tx] = src[r * KD + c0 + tx];
    }
    __syncthreads();
    #pragma unroll
    for (int i = 0; i < 4; i++) {
        int c  = c0 + ty + i * 8;
        int rr = r0 + tx;
        if (rr < N) dst[c * NMAX + rr] = tile[tx][ty + i * 8];
    }
}

// monotone value -> bucket map: linear over [-4,4], clamped
__device__ __forceinline__ int bucket_of(float v) {
    int bi = __float2int_rd(v * 64.0f + 256.0f);   // 64 buckets per unit
    return min(max(bi, 0), NB - 1);
}

// ---------------- fused: bucket counting-sort pair-sums + ALM + finalize ----
__global__ void __launch_bounds__(THREADS) fused_kernel(
    const float* __restrict__ s, const float* __restrict__ t,
    const void* __restrict__ rows_raw, const void* __restrict__ cols_raw,
    float* __restrict__ out, int Ns, int Nt, int nb)
{
    __shared__ float  ysc[PAD];       // y scattered in bucket order (Nt entries)
    __shared__ float  ypre[PAD + 1];  // element prefix: ypre[i] = sum of first i
    __shared__ int    bcnt[NB + 1];   // histogram -> exclusive prefix counts
    __shared__ int    iwarp[8];
    __shared__ float  fwarp[8];
    __shared__ double dwarp[8];
    __shared__ int    slast;

    const int tid  = threadIdx.x;
    const int lane = tid & 31;
    const int wid  = tid >> 5;
    const int b    = blockIdx.x;

    if (b >= KD) {
        // ======== ALM blocks: anchor-pair L1 sums, sliced over anchors ========
        __shared__ int is64;
        if (tid == 0) {
            const int* r32 = (const int*)rows_raw;
            is64 = (r32[1] == 0 && r32[3] == 0 && r32[5] == 0) ? 1 : 0;
        }
        __syncthreads();
        const int a = b - KD;
        const int chunk = (nb + ALM_BLOCKS - 1) / ALM_BLOCKS;
        const int lo = a * chunk, hi = min(nb, lo + chunk);
        const long long* r64 = (const long long*)rows_raw;
        const long long* c64 = (const long long*)cols_raw;
        const int* r32 = (const int*)rows_raw;
        const int* c32 = (const int*)cols_raw;
        double acc = 0.0;
        for (int bi = lo; bi < hi; bi++) {
            long long r = is64 ? r64[bi] : (long long)r32[bi];
            long long c = is64 ? c64[bi] : (long long)c32[bi];
            acc += (double)fabsf(s[r * KD + tid] - t[c * KD + tid]);
        }
        #pragma unroll
        for (int o = 16; o > 0; o >>= 1) acc += __shfl_down_sync(0xffffffffu, acc, o);
        if (lane == 0) dwarp[wid] = acc;
        __syncthreads();
        if (tid == 0) {
            #pragma unroll
            for (int k = 0; k < NRK; k++)
                g_almp[a * NRK + k] = dwarp[2 * k] + dwarp[2 * k + 1];
        }
    } else {
        // ======== column blocks: exact all-pairs L1 via bucket counting ======
        const float* ycol = g_tT + (size_t)b * NMAX;
        const float* xcol = g_sT + (size_t)b * NMAX;
        const int base = tid * ES;   // contiguous chunk ownership

        // zero histogram (2 buckets per thread)
        bcnt[2 * tid] = 0;
        bcnt[2 * tid + 1] = 0;
        if (tid == 0) bcnt[NB] = 0;

        // --- x load: 2 aligned float4 (mapping irrelevant; masked by index) ---
        float x[ES];
        {
            float4 a0 = *(const float4*)(xcol + base);
            float4 a1 = *(const float4*)(xcol + base + 4);
            x[0]=a0.x; x[1]=a0.y; x[2]=a0.z; x[3]=a0.w;
            x[4]=a1.x; x[5]=a1.y; x[6]=a1.z; x[7]=a1.w;
        }

        // --- y load: 2 aligned float4 ---
        float yv[ES];
        {
            float4 a0 = *(const float4*)(ycol + base);
            float4 a1 = *(const float4*)(ycol + base + 4);
            yv[0]=a0.x; yv[1]=a0.y; yv[2]=a0.z; yv[3]=a0.w;
            yv[4]=a1.x; yv[5]=a1.y; yv[6]=a1.z; yv[7]=a1.w;
        }
        __syncthreads();

        // histogram counts; atomic return value = within-bucket rank (free)
        int ybi[ES];
        int yrk[ES];
        #pragma unroll
        for (int m = 0; m < ES; m++) {
            if (base + m < Nt) {
                ybi[m] = bucket_of(yv[m]);
                yrk[m] = atomicAdd(&bcnt[ybi[m]], 1);
            }
        }
        __syncthreads();

        // exclusive scan of NB int counts: 2 per thread + shfl
        {
            const int c0 = bcnt[2 * tid], c1 = bcnt[2 * tid + 1];
            const int tc = c0 + c1;
            int ci = tc;
            #pragma unroll
            for (int o = 1; o < 32; o <<= 1) {
                int nc = __shfl_up_sync(0xffffffffu, ci, o);
                if (lane >= o) ci += nc;
            }
            if (lane == 31) iwarp[wid] = ci;
            __syncthreads();   // all bcnt reads done before overwrite
            int coff = 0;
            #pragma unroll
            for (int w = 0; w < 8; w++)
                if (w < wid) coff += iwarp[w];
            const int cbase = coff + ci - tc;
            bcnt[2 * tid]     = cbase;
            bcnt[2 * tid + 1] = cbase + c0;
            if (tid == THREADS - 1) bcnt[NB] = cbase + tc;   // = Nt
        }
        __syncthreads();

        // scatter: position = exclusive prefix + saved rank (no atomics)
        #pragma unroll
        for (int m = 0; m < ES; m++) {
            if (base + m < Nt)
                ysc[bcnt[ybi[m]] + yrk[m]] = yv[m];
        }
        __syncthreads();

        // element-level exclusive prefix over scattered y (pads -> 0)
        {
            float pre[ES];
            float run = 0.f;
            #pragma unroll
            for (int m = 0; m < ES; m++) {
                int idx = base + m;
                float vv = (idx < Nt) ? ysc[idx] : 0.f;
                run += vv;
                pre[m] = run;
            }
            float incl = run;
            #pragma unroll
            for (int o = 1; o < 32; o <<= 1) {
                float n = __shfl_up_sync(0xffffffffu, incl, o);
                if (lane >= o) incl += n;
            }
            if (lane == 31) fwarp[wid] = incl;
            const float excl = incl - run;
            __syncthreads();
            float woff = 0.f;
            #pragma unroll
            for (int w = 0; w < 8; w++)
                if (w < wid) woff += fwarp[w];
            const float off = woff + excl;
            #pragma unroll
            for (int m = 0; m < ES; m++) ypre[base + m + 1] = pre[m] + off;
            if (tid == 0) ypre[0] = 0.f;
        }
        __syncthreads();

        const float Ptot = ypre[Nt];

        // per-x: bucket-boundary prefix + exact partial-bucket scan
        double acc = 0.0;
        #pragma unroll
        for (int m = 0; m < ES; m++) {
            if (base + m >= Ns) continue;
            const float xv = x[m];
            const int bx  = bucket_of(xv);
            const int beg = bcnt[bx];
            const int end = bcnt[bx + 1];
            int   c = beg;
            float P = ypre[beg];   // sum of all y in buckets below bx
            for (int idx = beg; idx < end; idx++) {
                float yy = ysc[idx];
                if (yy <= xv) { c++; P += yy; }
            }
            acc += (double)(xv * (float)(2 * c - Nt) + Ptot - 2.f * P);
        }

        #pragma unroll
        for (int o = 16; o > 0; o >>= 1) acc += __shfl_down_sync(0xffffffffu, acc, o);
        if (lane == 0) dwarp[wid] = acc;
        __syncthreads();
        if (tid == 0) {
            double sum = 0.0;
            #pragma unroll
            for (int w = 0; w < 8; w++) sum += dwarp[w];
            g_colp[b] = sum;
        }
    }

    // ======== completion ticket: last block finalizes ========
    if (tid == 0) {
        __threadfence();
        int tk = atomicAdd(&g_count, 1);
        slast = (tk == TOTAL_BLOCKS - 1) ? 1 : 0;
    }
    __syncthreads();
    if (!slast) return;
    __threadfence();

    // reduce g_colp (256 doubles) by k-groups of 64
    double vv = g_colp[tid];
    #pragma unroll
    for (int o = 16; o > 0; o >>= 1) vv += __shfl_down_sync(0xffffffffu, vv, o);
    if (lane == 0) dwarp[wid] = vv;
    __syncthreads();
    if (tid == 0) {
        const double params[NRK] = {0.4, 0.2, 0.2, 0.2};
        const double EPS = 3.0;
        const double nb_notB = (double)Ns * (double)Nt - (double)nb;
        double ret = 0.0;
        #pragma unroll
        for (int k = 0; k < NRK; k++) {
            double all = dwarp[2 * k] + dwarp[2 * k + 1];
            double alm = 0.0;
            #pragma unroll
            for (int a = 0; a < ALM_BLOCKS; a++) alm += g_almp[a * NRK + k];
            double notalm = all - alm;
            double lk = alm * nb_notB + (EPS * nb_notB - notalm) * (double)nb;
            ret += params[k] * lk / (double)DW;
        }
        out[0] = (float)(ret / ((double)Ns * (double)Nt));
        g_count = 0;  // reset for next graph replay
    }
}

extern "C" void kernel_launch(void* const* d_in, const int* in_sizes, int n_in,
                              void* d_out, int out_size) {
    const float* s = (const float*)d_in[0];
    const float* t = (const float*)d_in[1];
    const void* rows = d_in[2];
    const void* cols = d_in[3];
    int Ns = in_sizes[0] / KD;
    int Nt = in_sizes[1] / KD;
    int nb = in_sizes[2];
    int nmax = Ns > Nt ? Ns : Nt;

    dim3 tgrid((nmax + 31) / 32, KD / 32, 2);
    dim3 tblk(32, 8, 1);
    transpose_kernel<<<tgrid, tblk>>>(s, t, Ns, Nt);
    fused_kernel<<<TOTAL_BLOCKS, THREADS>>>(s, t, rows, cols,
                                            (float*)d_out, Ns, Nt, nb);
}

// round 13
// speedup vs baseline: 1.0381x; 1.0381x over previous
#include <cuda_runtime.h>

#define NRK 4
#define DW  64
#define KD  256            // NR*D plane stride
#define THREADS 256
#define NB  512            // value buckets (width 1/64 over [-4,4])
#define ES  8              // elements per thread (contiguous chunk), Nt,Ns <= 2048
#define PAD 2048
#define ALM_BLOCKS 8
#define NMAX 2048          // padded column stride
#define TOTAL_BLOCKS (KD + ALM_BLOCKS)

// Static scratch (no allocation). Zero-init at load; pads never written -> 0.
__device__ float  g_sT[KD * NMAX];           // s transposed+padded: [KD][NMAX]
__device__ float  g_tT[KD * NMAX];           // t transposed+padded: [KD][NMAX]
__device__ double g_colp[KD];                // per-column partials
__device__ double g_almp[ALM_BLOCKS * NRK];  // per-block per-k anchor partials
__device__ int    g_count = 0;               // completion ticket (self-reset)

// ---------------- tiled transpose: [N][256] -> [256][NMAX] ----------------
__global__ void transpose_kernel(const float* __restrict__ s,
                                 const float* __restrict__ t,
                                 int Ns, int Nt) {
    __shared__ float tile[32][33];
    const float* src; float* dst; int N;
    if (blockIdx.z == 0) { src = s; dst = g_sT; N = Ns; }
    else                 { src = t; dst = g_tT; N = Nt; }
    const int tx = threadIdx.x, ty = threadIdx.y;  // 32 x 8
    const int r0 = blockIdx.x * 32, c0 = blockIdx.y * 32;
    #pragma unroll
    for (int i = 0; i < 4; i++) {
        int r = r0 + ty + i * 8;
        if (r < N) tile[ty + i * 8][tx] = src[r * KD + c0 + tx];
    }
    __syncthreads();
    #pragma unroll
    for (int i = 0; i < 4; i++) {
        int c  = c0 + ty + i * 8;
        int rr = r0 + tx;
        if (rr < N) dst[c * NMAX + rr] = tile[tx][ty + i * 8];
    }
}

// monotone value -> bucket map: linear over [-4,4], clamped
__device__ __forceinline__ int bucket_of(float v) {
    int bi = __float2int_rd(v * 64.0f + 256.0f);   // 64 buckets per unit
    return min(max(bi, 0), NB - 1);
}

// ---------------- fused: bucket counting-sort pair-sums + ALM + finalize ----
__global__ void __launch_bounds__(THREADS) fused_kernel(
    const float* __restrict__ s, const float* __restrict__ t,
    const void* __restrict__ rows_raw, const void* __restrict__ cols_raw,
    float* __restrict__ out, int Ns, int Nt, int nb)
{
    __shared__ float  ysc[PAD];       // y scattered in bucket order (Nt entries)
    __shared__ float  xsc[PAD];       // x scattered in bucket order (Ns entries)
    __shared__ float  ypre[PAD + 1];  // element prefix: ypre[i] = sum of first i
    __shared__ int    bcnt[NB + 1];   // y histogram -> exclusive prefix counts
    __shared__ int    xcnt[NB];       // x histogram (rank source only)
    __shared__ int    iwarp[8];
    __shared__ int    jwarp[8];
    __shared__ float  fwarp[8];
    __shared__ double dwarp[8];
    __shared__ int    slast;

    const int tid  = threadIdx.x;
    const int lane = tid & 31;
    const int wid  = tid >> 5;
    const int b    = blockIdx.x;

    if (b >= KD) {
        // ======== ALM blocks: anchor-pair L1 sums, sliced over anchors ========
        __shared__ int is64;
        if (tid == 0) {
            const int* r32 = (const int*)rows_raw;
            is64 = (r32[1] == 0 && r32[3] == 0 && r32[5] == 0) ? 1 : 0;
        }
        __syncthreads();
        const int a = b - KD;
        const int chunk = (nb + ALM_BLOCKS - 1) / ALM_BLOCKS;
        const int lo = a * chunk, hi = min(nb, lo + chunk);
        const long long* r64 = (const long long*)rows_raw;
        const long long* c64 = (const long long*)cols_raw;
        const int* r32 = (const int*)rows_raw;
        const int* c32 = (const int*)cols_raw;
        double acc = 0.0;
        for (int bi = lo; bi < hi; bi++) {
            long long r = is64 ? r64[bi] : (long long)r32[bi];
            long long c = is64 ? c64[bi] : (long long)c32[bi];
            acc += (double)fabsf(s[r * KD + tid] - t[c * KD + tid]);
        }
        #pragma unroll
        for (int o = 16; o > 0; o >>= 1) acc += __shfl_down_sync(0xffffffffu, acc, o);
        if (lane == 0) dwarp[wid] = acc;
        __syncthreads();
        if (tid == 0) {
            #pragma unroll
            for (int k = 0; k < NRK; k++)
                g_almp[a * NRK + k] = dwarp[2 * k] + dwarp[2 * k + 1];
        }
    } else {
        // ======== column blocks: exact all-pairs L1 via bucket counting ======
        const float* ycol = g_tT + (size_t)b * NMAX;
        const float* xcol = g_sT + (size_t)b * NMAX;
        const int base = tid * ES;   // contiguous chunk ownership

        // zero histograms (2 buckets per thread each)
        bcnt[2 * tid] = 0;  bcnt[2 * tid + 1] = 0;
        xcnt[2 * tid] = 0;  xcnt[2 * tid + 1] = 0;
        if (tid == 0) bcnt[NB] = 0;

        // --- loads: 2 aligned float4 each for x and y ---
        float x[ES], yv[ES];
        {
            float4 a0 = *(const float4*)(xcol + base);
            float4 a1 = *(const float4*)(xcol + base + 4);
            x[0]=a0.x; x[1]=a0.y; x[2]=a0.z; x[3]=a0.w;
            x[4]=a1.x; x[5]=a1.y; x[6]=a1.z; x[7]=a1.w;
            float4 b0 = *(const float4*)(ycol + base);
            float4 b1 = *(const float4*)(ycol + base + 4);
            yv[0]=b0.x; yv[1]=b0.y; yv[2]=b0.z; yv[3]=b0.w;
            yv[4]=b1.x; yv[5]=b1.y; yv[6]=b1.z; yv[7]=b1.w;
        }
        __syncthreads();

        // histogram counts; atomic return value = within-bucket rank (free)
        int ybi[ES], yrk[ES];
        int xbi[ES], xrk[ES];
        #pragma unroll
        for (int m = 0; m < ES; m++) {
            if (base + m < Nt) {
                ybi[m] = bucket_of(yv[m]);
                yrk[m] = atomicAdd(&bcnt[ybi[m]], 1);
            }
            if (base + m < Ns) {
                xbi[m] = bucket_of(x[m]);
                xrk[m] = atomicAdd(&xcnt[xbi[m]], 1);
            }
        }
        __syncthreads();

        // exclusive scans of both histograms (2 buckets/thread each, one pass)
        {
            const int c0 = bcnt[2 * tid], c1 = bcnt[2 * tid + 1];
            const int d0 = xcnt[2 * tid], d1 = xcnt[2 * tid + 1];
            const int tc = c0 + c1, td = d0 + d1;
            int ci = tc, di = td;
            #pragma unroll
            for (int o = 1; o < 32; o <<= 1) {
                int nc = __shfl_up_sync(0xffffffffu, ci, o);
                int nd = __shfl_up_sync(0xffffffffu, di, o);
                if (lane >= o) { ci += nc; di += nd; }
            }
            if (lane == 31) { iwarp[wid] = ci; jwarp[wid] = di; }
            __syncthreads();   // all histogram reads done before overwrite
            int coff = 0, doff = 0;
            #pragma unroll
            for (int w = 0; w < 8; w++)
                if (w < wid) { coff += iwarp[w]; doff += jwarp[w]; }
            const int cbase = coff + ci - tc;
            const int dbase = doff + di - td;
            bcnt[2 * tid]     = cbase;
            bcnt[2 * tid + 1] = cbase + c0;
            xcnt[2 * tid]     = dbase;
            xcnt[2 * tid + 1] = dbase + d0;
            if (tid == THREADS - 1) bcnt[NB] = cbase + tc;   // = Nt
        }
        __syncthreads();

        // scatter both into bucket order (no atomics: prefix + saved rank)
        #pragma unroll
        for (int m = 0; m < ES; m++) {
            if (base + m < Nt) ysc[bcnt[ybi[m]] + yrk[m]] = yv[m];
            if (base + m < Ns) xsc[xcnt[xbi[m]] + xrk[m]] = x[m];
        }
        __syncthreads();

        // element-level exclusive prefix over scattered y (pads -> 0)
        {
            float pre[ES];
            float run = 0.f;
            #pragma unroll
            for (int m = 0; m < ES; m++) {
                int idx = base + m;
                float vv = (idx < Nt) ? ysc[idx] : 0.f;
                run += vv;
                pre[m] = run;
            }
            float incl = run;
            #pragma unroll
            for (int o = 1; o < 32; o <<= 1) {
                float n = __shfl_up_sync(0xffffffffu, incl, o);
                if (lane >= o) incl += n;
            }
            if (lane == 31) fwarp[wid] = incl;
            const float excl = incl - run;
            __syncthreads();
            float woff = 0.f;
            #pragma unroll
            for (int w = 0; w < 8; w++)
                if (w < wid) woff += fwarp[w];
            const float off = woff + excl;
            #pragma unroll
            for (int m = 0; m < ES; m++) ypre[base + m + 1] = pre[m] + off;
            if (tid == 0) ypre[0] = 0.f;
        }
        __syncthreads();

        const float Ptot = ypre[Nt];

        // per-x search over bucket-SORTED x (strided: lanes hit adjacent
        // positions -> same/nearby buckets -> minimal warp divergence)
        double acc = 0.0;
        #pragma unroll
        for (int u = 0; u < ES; u++) {
            const int i = tid + u * THREADS;
            if (i >= Ns) continue;
            const float xv = xsc[i];
            const int bx  = bucket_of(xv);
            const int beg = bcnt[bx];
            const int end = bcnt[bx + 1];
            int   c = beg;
            float P = ypre[beg];   // sum of all y in buckets below bx
            for (int idx = beg; idx < end; idx++) {
                float yy = ysc[idx];
                if (yy <= xv) { c++; P += yy; }
            }
            acc += (double)(xv * (float)(2 * c - Nt) + Ptot - 2.f * P);
        }

        #pragma unroll
        for (int o = 16; o > 0; o >>= 1) acc += __shfl_down_sync(0xffffffffu, acc, o);
        if (lane == 0) dwarp[wid] = acc;
        __syncthreads();
        if (tid == 0) {
            double sum = 0.0;
            #pragma unroll
            for (int w = 0; w < 8; w++) sum += dwarp[w];
            g_colp[b] = sum;
        }
    }

    // ======== completion ticket: last block finalizes ========
    if (tid == 0) {
        __threadfence();
        int tk = atomicAdd(&g_count, 1);
        slast = (tk == TOTAL_BLOCKS - 1) ? 1 : 0;
    }
    __syncthreads();
    if (!slast) return;
    __threadfence();

    // reduce g_colp (256 doubles) by k-groups of 64
    double vv = g_colp[tid];
    #pragma unroll
    for (int o = 16; o > 0; o >>= 1) vv += __shfl_down_sync(0xffffffffu, vv, o);
    if (lane == 0) dwarp[wid] = vv;
    __syncthreads();
    if (tid == 0) {
        const double params[NRK] = {0.4, 0.2, 0.2, 0.2};
        const double EPS = 3.0;
        const double nb_notB = (double)Ns * (double)Nt - (double)nb;
        double ret = 0.0;
        #pragma unroll
        for (int k = 0; k < NRK; k++) {
            double all = dwarp[2 * k] + dwarp[2 * k + 1];
            double alm = 0.0;
            #pragma unroll
            for (int a = 0; a < ALM_BLOCKS; a++) alm += g_almp[a * NRK + k];
            double notalm = all - alm;
            double lk = alm * nb_notB + (EPS * nb_notB - notalm) * (double)nb;
            ret += params[k] * lk / (double)DW;
        }
        out[0] = (float)(ret / ((double)Ns * (double)Nt));
        g_count = 0;  // reset for next graph replay
    }
}

extern "C" void kernel_launch(void* const* d_in, const int* in_sizes, int n_in,
                              void* d_out, int out_size) {
    const float* s = (const float*)d_in[0];
    const float* t = (const float*)d_in[1];
    const void* rows = d_in[2];
    const void* cols = d_in[3];
    int Ns = in_sizes[0] / KD;
    int Nt = in_sizes[1] / KD;
    int nb = in_sizes[2];
    int nmax = Ns > Nt ? Ns : Nt;

    dim3 tgrid((nmax + 31) / 32, KD / 32, 2);
    dim3 tblk(32, 8, 1);
    transpose_kernel<<<tgrid, tblk>>>(s, t, Ns, Nt);
    fused_kernel<<<TOTAL_BLOCKS, THREADS>>>(s, t, rows, cols,
                                            (float*)d_out, Ns, Nt, nb);
}